// round 1
// baseline (speedup 1.0000x reference)
#include <cuda_runtime.h>
#include <cuda_bf16.h>

#define THREADS 512

// Scratch: boost factors (n <= 16384 supported; actual n = 4096)
__device__ float g_bf[16384];

__global__ void boost_kernel(const float* __restrict__ duty,
                             const int* __restrict__ kp, int n) {
    int i = blockIdx.x * blockDim.x + threadIdx.x;
    if (i < n) {
        float td = (float)(*kp) / (float)n;
        g_bf[i] = expf(td - duty[i]);   // boostStrength = 1.0
    }
}

// Monotone float -> uint key: key(a) >= key(b)  <=>  a >= b  (for non-NaN)
__device__ __forceinline__ unsigned f2key(float f) {
    unsigned u = __float_as_uint(f);
    return u ^ (unsigned)(((int)u >> 31) | 0x80000000);
}

template <int EPV>  // float4 elements per thread per row
__global__ __launch_bounds__(THREADS, 2)
void kwinner_kernel(const float* __restrict__ x,
                    const int* __restrict__ kp,
                    float* __restrict__ out, int n) {
    const int row = blockIdx.x;
    const int t   = threadIdx.x;

    __shared__ unsigned hist[256];
    __shared__ unsigned suf[256];
    __shared__ unsigned wtot[8];
    __shared__ unsigned wsuf[8];
    __shared__ unsigned sPrefix, sKr;

    const float4* xrow = (const float4*)(x + (size_t)row * n);
    const float4* bfv  = (const float4*)g_bf;

    float4   xv[EPV];
    unsigned key[EPV * 4];

    #pragma unroll
    for (int j = 0; j < EPV; j++) {
        int f = t + j * THREADS;
        xv[j] = xrow[f];
        float4 bf = bfv[f];
        key[j*4+0] = f2key(xv[j].x * bf.x);
        key[j*4+1] = f2key(xv[j].y * bf.y);
        key[j*4+2] = f2key(xv[j].z * bf.z);
        key[j*4+3] = f2key(xv[j].w * bf.w);
    }

    unsigned kr     = (unsigned)(*kp);
    unsigned prefix = 0;

    #pragma unroll
    for (int pass = 0; pass < 4; pass++) {
        const int shift = 24 - pass * 8;
        const unsigned pmask = (pass == 0) ? 0u : (0xFFFFFFFFu << (shift + 8));

        if (t < 256) hist[t] = 0;
        __syncthreads();

        // Histogram current byte of candidate keys (warp-aggregated atomics:
        // pass-0 digits of normal data collapse into a few exponent bins).
        #pragma unroll
        for (int e = 0; e < EPV * 4; e++) {
            unsigned kk = key[e];
            if ((kk & pmask) == prefix) {
                unsigned d = (kk >> shift) & 0xFFu;
                unsigned m = __match_any_sync(__activemask(), d);
                if ((t & 31) == (__ffs(m) - 1))
                    atomicAdd(&hist[d], (unsigned)__popc(m));
            }
        }
        __syncthreads();

        // Suffix sums over 256 bins: per-warp shfl suffix scan + 8-way combine.
        unsigned v = (t < 256) ? hist[t] : 0u;
        #pragma unroll
        for (int off = 1; off < 32; off <<= 1) {
            unsigned u = __shfl_down_sync(0xFFFFFFFFu, v, off);
            if ((t & 31) + off < 32) v += u;
        }
        if (t < 256 && (t & 31) == 0) wtot[t >> 5] = v;
        __syncthreads();
        if (t < 8) {
            unsigned s = 0;
            for (int j = t + 1; j < 8; j++) s += wtot[j];
            wsuf[t] = s;
        }
        __syncthreads();
        if (t < 256) suf[t] = v + wsuf[t >> 5];
        __syncthreads();
        if (t < 256) {
            unsigned S  = suf[t];
            unsigned Sn = (t < 255) ? suf[t + 1] : 0u;
            if (S >= kr && Sn < kr) {   // unique crossing bin
                sPrefix = prefix | ((unsigned)t << shift);
                sKr     = kr - Sn;
            }
        }
        __syncthreads();
        prefix = sPrefix;
        kr     = sKr;
        __syncthreads();
    }

    const unsigned thresh = prefix;  // exact key of the k-th largest boosted value

    float4* orow = (float4*)(out + (size_t)row * n);
    #pragma unroll
    for (int j = 0; j < EPV; j++) {
        int f = t + j * THREADS;
        float4 o;
        o.x = (key[j*4+0] >= thresh) ? xv[j].x : 0.0f;
        o.y = (key[j*4+1] >= thresh) ? xv[j].y : 0.0f;
        o.z = (key[j*4+2] >= thresh) ? xv[j].z : 0.0f;
        o.w = (key[j*4+3] >= thresh) ? xv[j].w : 0.0f;
        orow[f] = o;
    }
}

extern "C" void kernel_launch(void* const* d_in, const int* in_sizes, int n_in,
                              void* d_out, int out_size) {
    const float* x    = (const float*)d_in[0];
    const float* duty = (const float*)d_in[1];
    const int*   kp   = (const int*)d_in[2];
    float*       out  = (float*)d_out;

    int n    = in_sizes[1];          // 4096
    int rows = in_sizes[0] / n;      // 8192

    boost_kernel<<<(n + 255) / 256, 256>>>(duty, kp, n);

    int epv = n / (THREADS * 4);
    switch (epv) {
        case 1: kwinner_kernel<1><<<rows, THREADS>>>(x, kp, out, n); break;
        case 2: kwinner_kernel<2><<<rows, THREADS>>>(x, kp, out, n); break;
        case 4: kwinner_kernel<4><<<rows, THREADS>>>(x, kp, out, n); break;
        case 8: kwinner_kernel<8><<<rows, THREADS>>>(x, kp, out, n); break;
        default: break; // unsupported shape (not expected for this problem)
    }
}

// round 2
// speedup vs baseline: 1.2582x; 1.2582x over previous
#include <cuda_runtime.h>
#include <cuda_bf16.h>

#define THREADS 512
#define NWARP   16
#define CAP     3072

// Scratch: boost factors (n <= 16384 supported; actual n = 4096)
__device__ float g_bf[16384];

__global__ void boost_kernel(const float* __restrict__ duty,
                             const int* __restrict__ kp, int n) {
    int i = blockIdx.x * blockDim.x + threadIdx.x;
    if (i < n) {
        float td = (float)(*kp) / (float)n;
        g_bf[i] = expf(td - duty[i]);   // boostStrength = 1.0
    }
}

// Monotone float -> uint key: key(a) >= key(b)  <=>  a >= b  (for non-NaN)
__device__ __forceinline__ unsigned f2key(float f) {
    unsigned u = __float_as_uint(f);
    return u ^ (unsigned)(((int)u >> 31) | 0x80000000);
}

struct Sm {
    unsigned hist[4096];
    unsigned list[CAP];
    unsigned wtot[NWARP];
    unsigned wsuf[NWARP];
    unsigned sPrefix, sKr, sCnt, sNum, sThr;
};

// One histogram level: NB bins on key bits [SH+log2(NB)-1 : SH].
// Candidates are keys matching `prefix` on bits [31 : SHTOP].
// Updates prefix/kr and C = #keys in the crossing bin.
template <int NK, int NB, int SH, int SHTOP>
__device__ __forceinline__ void select_level(const unsigned (&key)[NK], Sm* s,
                                             unsigned& prefix, unsigned& kr,
                                             unsigned& C) {
    const int t    = threadIdx.x;
    const int lane = t & 31;
    const int wid  = t >> 5;
    constexpr int BPT = NB / THREADS;   // bins per thread

    #pragma unroll
    for (int i = 0; i < BPT; i++) s->hist[t + i * THREADS] = 0;
    __syncthreads();

    #pragma unroll
    for (int e = 0; e < NK; e++) {
        unsigned kk = key[e];
        bool cand = (SHTOP >= 32) || (((kk ^ prefix) >> (SHTOP & 31)) == 0);
        if (cand) atomicAdd(&s->hist[(kk >> SH) & (NB - 1)], 1u);
    }
    __syncthreads();

    // Suffix counts: thread t owns bins [t*BPT, (t+1)*BPT)
    unsigned base = (unsigned)t * BPT;
    unsigned h[BPT];
    unsigned tot = 0;
    #pragma unroll
    for (int i = 0; i < BPT; i++) { h[i] = s->hist[base + i]; tot += h[i]; }

    // warp suffix scan of chunk totals (v = sum of lanes lane..31)
    unsigned v = tot;
    #pragma unroll
    for (int off = 1; off < 32; off <<= 1) {
        unsigned u = __shfl_down_sync(0xFFFFFFFFu, v, off);
        if (lane + off < 32) v += u;
    }
    if (lane == 0) s->wtot[wid] = v;
    __syncthreads();
    if (t < NWARP) {
        unsigned sum = 0;
        for (int j = t + 1; j < NWARP; j++) sum += s->wtot[j];
        s->wsuf[t] = sum;
    }
    __syncthreads();

    unsigned run = s->wsuf[wid] + (v - tot);   // suffix from higher chunks
    #pragma unroll
    for (int i = BPT - 1; i >= 0; i--) {
        unsigned nxt = run;     // suffix(base+i+1)
        run += h[i];            // suffix(base+i)
        if (run >= kr && nxt < kr) {   // unique crossing bin
            s->sPrefix = prefix | ((base + (unsigned)i) << SH);
            s->sKr     = kr - nxt;
            s->sCnt    = h[i];
        }
    }
    __syncthreads();
    prefix = s->sPrefix;
    kr     = s->sKr;
    C      = s->sCnt;
    __syncthreads();
}

template <int EPV>  // float4 elements per thread per row
__global__ __launch_bounds__(THREADS, 3)
void kwinner_kernel(const float* __restrict__ x,
                    const int* __restrict__ kp,
                    float* __restrict__ out, int n) {
    const int row  = blockIdx.x;
    const int t    = threadIdx.x;
    const int lane = t & 31;
    const int wid  = t >> 5;

    __shared__ Sm s;

    const float4* xrow = (const float4*)(x + (size_t)row * n);
    const float4* bfv  = (const float4*)g_bf;

    float4   xv[EPV];
    unsigned key[EPV * 4];

    #pragma unroll
    for (int j = 0; j < EPV; j++) {
        int f = t + j * THREADS;
        xv[j] = xrow[f];
        float4 bf = bfv[f];
        key[j*4+0] = f2key(xv[j].x * bf.x);
        key[j*4+1] = f2key(xv[j].y * bf.y);
        key[j*4+2] = f2key(xv[j].z * bf.z);
        key[j*4+3] = f2key(xv[j].w * bf.w);
    }

    unsigned kr     = (unsigned)(*kp);
    unsigned prefix = 0;
    unsigned C      = 0;
    int remShift;

    // Level 0: top 12 bits. Common case exits here with C ~ tens.
    select_level<EPV*4, 4096, 20, 32>(key, &s, prefix, kr, C);
    remShift = 20;
    if (C > CAP) {   // degenerate data fallback (exactness guarantee)
        select_level<EPV*4, 1024, 10, 20>(key, &s, prefix, kr, C);
        remShift = 10;
        if (C > CAP) {
            select_level<EPV*4, 1024, 0, 10>(key, &s, prefix, kr, C);
            remShift = 0;
        }
    }

    unsigned thresh;
    if (remShift == 0) {
        thresh = prefix;   // all 32 bits resolved
    } else {
        // Compact crossing-bin candidates to smem
        if (t == 0) s.sNum = 0;
        __syncthreads();
        #pragma unroll
        for (int e = 0; e < EPV * 4; e++) {
            unsigned kk = key[e];
            if (((kk ^ prefix) >> remShift) == 0) {
                unsigned p = atomicAdd(&s.sNum, 1u);
                if (p < CAP) s.list[p] = kk;
            }
        }
        __syncthreads();

        // Warp 0: greedy MSB bit-descent for the remaining bits.
        // thr ends as the kr-th largest candidate key (exact).
        if (wid == 0) {
            unsigned thr = prefix;
            unsigned krr = kr;
            unsigned Cc  = s.sNum;   // <= CAP guaranteed by level logic
            for (int b = remShift - 1; b >= 0; b--) {
                unsigned test = thr | (1u << b);
                int cnt = 0;
                for (unsigned j = lane; j < Cc; j += 32)
                    cnt += (s.list[j] >= test) ? 1 : 0;
                cnt = __reduce_add_sync(0xFFFFFFFFu, cnt);
                if ((unsigned)cnt >= krr) thr = test;
            }
            if (lane == 0) s.sThr = thr;
        }
        __syncthreads();
        thresh = s.sThr;
    }

    float4* orow = (float4*)(out + (size_t)row * n);
    #pragma unroll
    for (int j = 0; j < EPV; j++) {
        int f = t + j * THREADS;
        float4 o;
        o.x = (key[j*4+0] >= thresh) ? xv[j].x : 0.0f;
        o.y = (key[j*4+1] >= thresh) ? xv[j].y : 0.0f;
        o.z = (key[j*4+2] >= thresh) ? xv[j].z : 0.0f;
        o.w = (key[j*4+3] >= thresh) ? xv[j].w : 0.0f;
        orow[f] = o;
    }
}

extern "C" void kernel_launch(void* const* d_in, const int* in_sizes, int n_in,
                              void* d_out, int out_size) {
    const float* x    = (const float*)d_in[0];
    const float* duty = (const float*)d_in[1];
    const int*   kp   = (const int*)d_in[2];
    float*       out  = (float*)d_out;

    int n    = in_sizes[1];          // 4096
    int rows = in_sizes[0] / n;      // 8192

    boost_kernel<<<(n + 255) / 256, 256>>>(duty, kp, n);

    int epv = n / (THREADS * 4);
    switch (epv) {
        case 1: kwinner_kernel<1><<<rows, THREADS>>>(x, kp, out, n); break;
        case 2: kwinner_kernel<2><<<rows, THREADS>>>(x, kp, out, n); break;
        case 4: kwinner_kernel<4><<<rows, THREADS>>>(x, kp, out, n); break;
        case 8: kwinner_kernel<8><<<rows, THREADS>>>(x, kp, out, n); break;
        default: break; // unsupported shape (not expected for this problem)
    }
}

// round 3
// speedup vs baseline: 1.5180x; 1.2065x over previous
#include <cuda_runtime.h>
#include <cuda_bf16.h>

#define THREADS 256
#define NWARP   (THREADS / 32)
#define NB      4096

// Scratch: boost factors and reciprocals (n <= 16384; actual n = 4096)
__device__ float g_bf[16384];
__device__ float g_ibf[16384];

__global__ void boost_kernel(const float* __restrict__ duty,
                             const int* __restrict__ kp, int n) {
    int i = blockIdx.x * blockDim.x + threadIdx.x;
    if (i < n) {
        float td = (float)(*kp) / (float)n;
        float b = expf(td - duty[i]);   // boostStrength = 1.0
        g_bf[i]  = b;
        g_ibf[i] = 1.0f / b;
    }
}

// Monotone float -> uint key: key(a) >= key(b)  <=>  a >= b  (for non-NaN)
__device__ __forceinline__ unsigned f2key(float f) {
    unsigned u = __float_as_uint(f);
    return u ^ (unsigned)(((int)u >> 31) | 0x80000000);
}
// Inverse transform
__device__ __forceinline__ float key2f(unsigned k) {
    unsigned m = ((int)k < 0) ? 0x80000000u : 0xFFFFFFFFu;
    return __uint_as_float(k ^ m);
}

struct Sm {
    union {
        unsigned hist[NB];   // level-0 histogram (12-bit digits)
        unsigned list[NB];   // crossing-bin candidates (hist is dead by then)
    };
    unsigned wtot[NWARP];
    unsigned sPrefix, sKr, sNum, sThr;
};

template <int EPV>  // float4 elements per thread per row
__global__ __launch_bounds__(THREADS, 6)
void kwinner_kernel(const float* __restrict__ x,
                    const int* __restrict__ kp,
                    float* __restrict__ out, int n) {
    const int row  = blockIdx.x;
    const int t    = threadIdx.x;
    const int lane = t & 31;
    const int wid  = t >> 5;
    constexpr int NK  = EPV * 4;
    constexpr int BPT = NB / THREADS;   // 16 bins per thread

    __shared__ Sm s;

    const float4* xrow = (const float4*)(x + (size_t)row * n);
    const float4* bfv  = (const float4*)g_bf;

    unsigned key[NK];

    // Zero histogram (uint4 stores) before using it
    {
        uint4* hz = (uint4*)s.hist;
        #pragma unroll
        for (int i = 0; i < NB / 4 / THREADS; i++)
            hz[t + i * THREADS] = make_uint4(0, 0, 0, 0);
    }

    // Load x, boost, transform to keys (x itself is NOT kept in registers)
    #pragma unroll
    for (int j = 0; j < EPV; j++) {
        int f = t + j * THREADS;
        float4 xv = xrow[f];
        float4 bf = bfv[f];
        key[j*4+0] = f2key(xv.x * bf.x);
        key[j*4+1] = f2key(xv.y * bf.y);
        key[j*4+2] = f2key(xv.z * bf.z);
        key[j*4+3] = f2key(xv.w * bf.w);
    }
    __syncthreads();   // hist zeroed

    // 12-bit histogram of all keys
    #pragma unroll
    for (int e = 0; e < NK; e++)
        atomicAdd(&s.hist[key[e] >> 20], 1u);
    __syncthreads();

    const unsigned k0 = (unsigned)(*kp);

    // Suffix-count scan over 4096 bins; thread t owns bins [t*BPT, (t+1)*BPT)
    unsigned base = (unsigned)t * BPT;
    unsigned tot = 0;
    {
        const uint4* hv = (const uint4*)(s.hist + base);
        #pragma unroll
        for (int i = 0; i < BPT / 4; i++) {
            uint4 h4 = hv[i];
            tot += h4.x + h4.y + h4.z + h4.w;
        }
    }
    // warp suffix scan of chunk totals (v = sum of lanes lane..31)
    unsigned v = tot;
    #pragma unroll
    for (int off = 1; off < 32; off <<= 1) {
        unsigned u = __shfl_down_sync(0xFFFFFFFFu, v, off);
        if (lane + off < 32) v += u;
    }
    if (lane == 0) s.wtot[wid] = v;
    if (t == 0) s.sNum = 0;
    __syncthreads();

    unsigned run = v - tot;                 // suffix within warp, above own chunk
    for (int j = wid + 1; j < NWARP; j++)   // higher warps (broadcast reads)
        run += s.wtot[j];

    // Find the unique crossing bin (suffix >= k0 > next suffix)
    #pragma unroll
    for (int i = BPT - 1; i >= 0; i--) {
        unsigned h  = s.hist[base + i];
        unsigned nxt = run;
        run += h;
        if (run >= k0 && nxt < k0) {
            s.sPrefix = (base + (unsigned)i) << 20;
            s.sKr     = k0 - nxt;
        }
    }
    __syncthreads();
    const unsigned prefix = s.sPrefix;
    const unsigned kr     = s.sKr;
    __syncthreads();   // everyone done reading hist -> list may overwrite

    // Compact crossing-bin candidates into smem (overlays hist)
    #pragma unroll
    for (int e = 0; e < NK; e++) {
        unsigned kk = key[e];
        if (((kk ^ prefix) >> 20) == 0)
            s.list[atomicAdd(&s.sNum, 1u)] = kk;
    }
    __syncthreads();
    const unsigned C = s.sNum;

    // Parallel rank selection: candidate with (gt < kr <= ge) is the kr-th
    // largest in the bin == overall k-th largest boosted value. Broadcast
    // inner loop, no serial cross-lane dependence.
    for (unsigned i = t; i < C; i += THREADS) {
        unsigned ki = s.list[i];
        unsigned gt = 0, ge = 0;
        #pragma unroll 8
        for (unsigned j = 0; j < C; j++) {
            unsigned lj = s.list[j];
            gt += (lj > ki)  ? 1u : 0u;
            ge += (lj >= ki) ? 1u : 0u;
        }
        if (gt < kr && ge >= kr) s.sThr = ki;   // ties write same value
    }
    __syncthreads();
    const unsigned thresh = s.sThr;

    // Output: reconstruct x = boosted / bf (<=2ulp; tolerance is 1e-3)
    float4* orow = (float4*)(out + (size_t)row * n);
    const float4* ibfv = (const float4*)g_ibf;
    #pragma unroll
    for (int j = 0; j < EPV; j++) {
        int f = t + j * THREADS;
        float4 ib = ibfv[f];
        float4 o;
        o.x = (key[j*4+0] >= thresh) ? key2f(key[j*4+0]) * ib.x : 0.0f;
        o.y = (key[j*4+1] >= thresh) ? key2f(key[j*4+1]) * ib.y : 0.0f;
        o.z = (key[j*4+2] >= thresh) ? key2f(key[j*4+2]) * ib.z : 0.0f;
        o.w = (key[j*4+3] >= thresh) ? key2f(key[j*4+3]) * ib.w : 0.0f;
        orow[f] = o;
    }
}

extern "C" void kernel_launch(void* const* d_in, const int* in_sizes, int n_in,
                              void* d_out, int out_size) {
    const float* x    = (const float*)d_in[0];
    const float* duty = (const float*)d_in[1];
    const int*   kp   = (const int*)d_in[2];
    float*       out  = (float*)d_out;

    int n    = in_sizes[1];          // 4096
    int rows = in_sizes[0] / n;      // 8192

    boost_kernel<<<(n + 255) / 256, 256>>>(duty, kp, n);

    int epv = n / (THREADS * 4);
    switch (epv) {
        case 1:  kwinner_kernel<1><<<rows, THREADS>>>(x, kp, out, n);  break;
        case 2:  kwinner_kernel<2><<<rows, THREADS>>>(x, kp, out, n);  break;
        case 4:  kwinner_kernel<4><<<rows, THREADS>>>(x, kp, out, n);  break;
        case 8:  kwinner_kernel<8><<<rows, THREADS>>>(x, kp, out, n);  break;
        case 16: kwinner_kernel<16><<<rows, THREADS>>>(x, kp, out, n); break;
        default: break; // unsupported shape (not expected for this problem)
    }
}